// round 4
// baseline (speedup 1.0000x reference)
#include <cuda_runtime.h>

// Problem constants (match reference)
#define NB   256
#define NK   64
#define NL   32
#define SENT 32          // SENTINEL = L
#define HALF 64
#define M    2048        // NK * NL entries per batch per side

// Hash table: open addressing, linear probe. Max 2048 distinct keys -> 50% load.
#define HSIZE 4096
#define HMASK 4095
#define EMPTY 0x7FFFFFFF
#define NODE_MASK 0x1FFFF   // node ids < 100000 < 2^17

#define NTHREADS 512
#define SPLIT 4             // CTAs per batch (wave balance: 1024 CTAs over 148 SMs)

__device__ __forceinline__ unsigned hslot(int node) {
    // Knuth multiplicative hash, top 12 bits
    return ((unsigned)node * 2654435761u) >> 20;
}

// Scatter-min insert: entry = (pos << 17) | node. Smaller pos == smaller entry
// (node bits equal), so atomicMin on the packed word is exact.
__device__ __forceinline__ void hinsert(int* tab, int node, int pos) {
    int v = (pos << 17) | node;
    unsigned s = hslot(node);
    while (true) {
        int cur = tab[s];
        if (cur == EMPTY) {
            int old = atomicCAS(&tab[s], EMPTY, v);
            if (old == EMPTY) return;     // claimed fresh slot
            cur = old;                    // raced; re-examine winner
        }
        if ((cur & NODE_MASK) == node) {  // same key -> min-combine
            atomicMin(&tab[s], v);
            return;
        }
        s = (s + 1) & HMASK;              // different key -> probe on
    }
}

__device__ __forceinline__ int hlookup(const int* tab, int node) {
    unsigned s = hslot(node);
    while (true) {
        int e = tab[s];
        if (e == EMPTY) return SENT;                   // never seen -> sentinel
        if ((e & NODE_MASK) == node) return e >> 17;   // min position
        s = (s + 1) & HMASK;
    }
}

__global__ __launch_bounds__(NTHREADS)
void wpe_kernel(const int* __restrict__ src_walks,
                const int* __restrict__ tgt_walks,
                const int* __restrict__ src_lens,
                const int* __restrict__ tgt_lens,
                const float* __restrict__ own_emb,    // (L+1, HALF)
                const float* __restrict__ cross_emb,  // (L+1, HALF)
                float* __restrict__ out)              // [src_pos | tgt_pos]
{
    __shared__ int tab_s[HSIZE];   // src saw-table
    __shared__ int tab_t[HSIZE];   // tgt saw-table

    const int b    = blockIdx.x / SPLIT;
    const int part = blockIdx.x % SPLIT;
    const int tid  = threadIdx.x;

    // ---- init hash tables ----
    #pragma unroll
    for (int i = tid; i < HSIZE; i += NTHREADS) {
        tab_s[i] = EMPTY;
        tab_t[i] = EMPTY;
    }
    __syncthreads();

    const int* sw = src_walks + b * M;
    const int* tw = tgt_walks + b * M;
    const int* sl = src_lens  + b * NK;
    const int* tl = tgt_lens  + b * NK;

    // ---- build both tables (scatter-min of walk position) ----
    // Valid entry: position l < len[k] AND node != 0. Invalid entries scatter
    // SENTINEL in the reference, which is a no-op on a SENTINEL-initialized
    // table, so we skip them entirely.
    for (int m = tid; m < M; m += NTHREADS) {
        const int k = m >> 5;
        const int l = m & 31;
        const int n1 = sw[m];
        if (l < sl[k] && n1 != 0) hinsert(tab_s, n1, l);
        const int n2 = tw[m];
        if (l < tl[k] && n2 != 0) hinsert(tab_t, n2, l);
    }
    __syncthreads();

    // ---- gather + embed + store ----
    // Row r in [0, 2M): r < M -> src_pos row, else tgt_pos row.
    // One warp per row: 128 floats = 32 * float4, one float4 per lane
    // (coalesced 512B STG.128 burst per row).
    const int warp  = tid >> 5;
    const int lane  = tid & 31;
    const int nwarp = NTHREADS / 32;          // 16
    const int rows_per_part = (2 * M) / SPLIT; // 1024
    const int r0 = part * rows_per_part;

    for (int r = r0 + warp; r < r0 + rows_per_part; r += nwarp) {
        const int side = (r >= M);            // 0 = src, 1 = tgt
        const int m = r & (M - 1);
        const int k = m >> 5;
        const int l = m & 31;

        int node, len;
        if (!side) { node = sw[m]; len = sl[k]; }
        else       { node = tw[m]; len = tl[k]; }

        float4 v;
        if (l >= len || node == 0) {
            // invalid entry: reference zeroes the whole 128-vector
            v = make_float4(0.f, 0.f, 0.f, 0.f);
        } else {
            // own-perspective table = this side's table; cross = other side's
            const int own   = hlookup(side ? tab_t : tab_s, node);
            const int cross = hlookup(side ? tab_s : tab_t, node);
            // lanes 0..15 -> own_emb[own] (64 floats); 16..31 -> cross_emb[cross]
            const float* src = (lane < 16)
                ? own_emb   + own   * HALF + lane * 4
                : cross_emb + cross * HALF + (lane - 16) * 4;
            v = *reinterpret_cast<const float4*>(src);
        }

        const long long obase =
            ((long long)(side ? NB * M : 0) + (long long)b * M + m) * 128;
        *reinterpret_cast<float4*>(out + obase + lane * 4) = v;
    }
}

extern "C" void kernel_launch(void* const* d_in, const int* in_sizes, int n_in,
                              void* d_out, int out_size) {
    const int*   src_walks = (const int*)d_in[0];
    const int*   tgt_walks = (const int*)d_in[1];
    const int*   src_lens  = (const int*)d_in[2];
    const int*   tgt_lens  = (const int*)d_in[3];
    const float* own_emb   = (const float*)d_in[4];
    const float* cross_emb = (const float*)d_in[5];
    float*       out       = (float*)d_out;

    wpe_kernel<<<NB * SPLIT, NTHREADS>>>(src_walks, tgt_walks,
                                         src_lens, tgt_lens,
                                         own_emb, cross_emb, out);
}

// round 5
// speedup vs baseline: 1.3188x; 1.3188x over previous
#include <cuda_runtime.h>

// Problem constants (match reference)
#define NB   256
#define NK   64
#define NL   32
#define SENT 32          // SENTINEL = L
#define HALF 64
#define M    2048        // NK * NL entries per batch per side
#define BM   (NB * M)    // rows per side = 524288

// Hash table: open addressing, linear probe. Max 2048 distinct keys -> 50% load.
#define HSIZE 4096
#define HMASK 4095
#define EMPTY 0x7FFFFFFF
#define NODE_MASK 0x1FFFF   // node ids < 100000 < 2^17

#define INVALID_CODE 0xFFFFu

// Scratch: packed (own | cross<<6) per entry, 0xFFFF = invalid row.
// Layout: [b][side][m]  (b*4096 + side*2048 + m)
__device__ unsigned short g_codes[NB * 2 * M];

__device__ __forceinline__ unsigned hslot(int node) {
    return ((unsigned)node * 2654435761u) >> 20;   // top 12 bits
}

// Scatter-min insert: entry = (pos << 17) | node. Same node -> node bits equal,
// so atomicMin on the packed word is an exact position-min.
__device__ __forceinline__ void hinsert(int* tab, int node, int pos) {
    int v = (pos << 17) | node;
    unsigned s = hslot(node);
    while (true) {
        int cur = tab[s];
        if (cur == EMPTY) {
            int old = atomicCAS(&tab[s], EMPTY, v);
            if (old == EMPTY) return;
            cur = old;
        }
        if ((cur & NODE_MASK) == node) {
            atomicMin(&tab[s], v);
            return;
        }
        s = (s + 1) & HMASK;
    }
}

__device__ __forceinline__ int hlookup(const int* tab, int node) {
    unsigned s = hslot(node);
    while (true) {
        int e = tab[s];
        if (e == EMPTY) return SENT;
        if ((e & NODE_MASK) == node) return e >> 17;
        s = (s + 1) & HMASK;
    }
}

// ─────────────────────────────────────────────────────────────────────────
// Kernel A: one CTA per batch. Build both saw-tables, resolve every entry to
// a packed 12-bit (own, cross) code in global scratch.
// ─────────────────────────────────────────────────────────────────────────
__global__ __launch_bounds__(512)
void resolve_kernel(const int* __restrict__ src_walks,
                    const int* __restrict__ tgt_walks,
                    const int* __restrict__ src_lens,
                    const int* __restrict__ tgt_lens)
{
    __shared__ int tab_s[HSIZE];
    __shared__ int tab_t[HSIZE];

    const int b   = blockIdx.x;
    const int tid = threadIdx.x;

    for (int i = tid; i < HSIZE; i += 512) {
        tab_s[i] = EMPTY;
        tab_t[i] = EMPTY;
    }
    __syncthreads();

    const int* sw = src_walks + b * M;
    const int* tw = tgt_walks + b * M;
    const int* sl = src_lens  + b * NK;
    const int* tl = tgt_lens  + b * NK;

    // Build: invalid entries scatter SENTINEL in the reference (no-op on a
    // SENTINEL-initialized table) -> skip them.
    for (int m = tid; m < M; m += 512) {
        const int k = m >> 5;
        const int l = m & 31;
        const int n1 = sw[m];
        if (l < sl[k] && n1 != 0) hinsert(tab_s, n1, l);
        const int n2 = tw[m];
        if (l < tl[k] && n2 != 0) hinsert(tab_t, n2, l);
    }
    __syncthreads();

    // Resolve all 2*M entries to codes.
    unsigned short* codes = g_codes + b * (2 * M);
    for (int e = tid; e < 2 * M; e += 512) {
        const int side = e >> 11;        // 0 = src, 1 = tgt
        const int m = e & (M - 1);
        const int k = m >> 5;
        const int l = m & 31;

        int node, len;
        if (!side) { node = sw[m]; len = sl[k]; }
        else       { node = tw[m]; len = tl[k]; }

        unsigned short c;
        if (l >= len || node == 0) {
            c = INVALID_CODE;
        } else {
            const int own   = hlookup(side ? tab_t : tab_s, node);
            const int cross = hlookup(side ? tab_s : tab_t, node);
            c = (unsigned short)(own | (cross << 6));
        }
        codes[e] = c;
    }
}

// ─────────────────────────────────────────────────────────────────────────
// Kernel B: pure expansion / store stream. One warp handles 4 consecutive
// output rows (4 x 512B contiguous STG.128). No smem, no hashing.
// ─────────────────────────────────────────────────────────────────────────
#define B_THREADS 256
#define ROWS_PER_WARP 4

__global__ __launch_bounds__(B_THREADS)
void expand_kernel(const float* __restrict__ own_emb,    // (33, 64)
                   const float* __restrict__ cross_emb,  // (33, 64)
                   float* __restrict__ out)              // [src_pos | tgt_pos]
{
    const int warp_g = (blockIdx.x * B_THREADS + threadIdx.x) >> 5;
    const int lane   = threadIdx.x & 31;

    const long long row0 = (long long)warp_g * ROWS_PER_WARP;
    // row r: side = r >= BM; b = (r % BM) / M; m = r % M.
    // The 4 rows share (side, b) and have consecutive m (M, BM divisible by 4).
    const int side = (row0 >= BM);
    const long long rem = side ? (row0 - BM) : row0;
    const int b = (int)(rem >> 11);       // rem / M
    const int m0 = (int)(rem & (M - 1));

    // Fetch 4 codes (lanes 0-3), broadcast via shfl.
    const unsigned short* cptr = g_codes + b * (2 * M) + side * M + m0;
    unsigned short myc = (lane < ROWS_PER_WARP) ? cptr[lane] : 0;

    // Per-lane embedding base: lanes 0-15 read own_emb, 16-31 read cross_emb.
    const bool lo = (lane < 16);
    const float* ebase = lo ? own_emb : cross_emb;
    const int eoff = (lo ? lane : (lane - 16)) * 4;

    float* orow = out + row0 * 128 + lane * 4;

    #pragma unroll
    for (int i = 0; i < ROWS_PER_WARP; i++) {
        const unsigned c = __shfl_sync(0xFFFFFFFFu, myc, i);
        float4 v;
        if (c == INVALID_CODE) {
            v = make_float4(0.f, 0.f, 0.f, 0.f);
        } else {
            const int idx = lo ? (c & 63) : (c >> 6);   // own : cross
            v = __ldg(reinterpret_cast<const float4*>(ebase + idx * HALF + eoff));
        }
        __stcs(reinterpret_cast<float4*>(orow + (long long)i * 128), v);
    }
}

extern "C" void kernel_launch(void* const* d_in, const int* in_sizes, int n_in,
                              void* d_out, int out_size) {
    const int*   src_walks = (const int*)d_in[0];
    const int*   tgt_walks = (const int*)d_in[1];
    const int*   src_lens  = (const int*)d_in[2];
    const int*   tgt_lens  = (const int*)d_in[3];
    const float* own_emb   = (const float*)d_in[4];
    const float* cross_emb = (const float*)d_in[5];
    float*       out       = (float*)d_out;

    resolve_kernel<<<NB, 512>>>(src_walks, tgt_walks, src_lens, tgt_lens);

    const long long total_rows = 2LL * BM;                       // 1,048,576
    const int warps  = (int)(total_rows / ROWS_PER_WARP);        // 262,144
    const int blocks = warps / (B_THREADS / 32);                 // 32,768
    expand_kernel<<<blocks, B_THREADS>>>(own_emb, cross_emb, out);
}